// round 10
// baseline (speedup 1.0000x reference)
#include <cuda_runtime.h>

#define DEGREE   6
#define WIDTH    7          // DEGREE - START_DEGREE + 1
#define FEAT     1024       // in_features
#define OUTF     1024       // out_features
#define THREADS  256
#define NWARPS   8
#define ROWS_PER_BLOCK 4    // 2 warps per row, 16 features per lane
#define GRID     592        // 148 SMs x 4 resident blocks
#define NGROUPS  (4096 / ROWS_PER_BLOCK)   // 1024

typedef unsigned long long u64;
union uf2 { u64 u; float2 f; };

// ---- packed f32x2 helpers (sm_103a, PTX-only; u64 keeps pairs aligned) ----
__device__ __forceinline__ u64 pack2(float lo, float hi) {
    u64 r; asm("mov.b64 %0, {%1, %2};" : "=l"(r) : "f"(lo), "f"(hi)); return r;
}
__device__ __forceinline__ u64 mul2(u64 a, u64 b) {
    u64 r; asm("mul.rn.f32x2 %0, %1, %2;" : "=l"(r) : "l"(a), "l"(b)); return r;
}
__device__ __forceinline__ u64 add2(u64 a, u64 b) {
    u64 r; asm("add.rn.f32x2 %0, %1, %2;" : "=l"(r) : "l"(a), "l"(b)); return r;
}
__device__ __forceinline__ u64 fma2(u64 a, u64 b, u64 c) {
    u64 r; asm("fma.rn.f32x2 %0, %1, %2, %3;" : "=l"(r) : "l"(a), "l"(b), "l"(c)); return r;
}
__device__ __forceinline__ float ex2f(float x) {
    float r; asm("ex2.approx.f32 %0, %1;" : "=f"(r) : "f"(x)); return r;
}
__device__ __forceinline__ float clipf(float v) {
    return fminf(fmaxf(v, -100.0f), 100.0f);
}

// ---------- packed phase-1 eval: 16 features -> 7 scalar partial sums ------
__device__ __forceinline__ void eval16p(const float4* __restrict__ xv,
                                        u64 tis2, u64 k2, u64 m2,
                                        float* __restrict__ aout)
{
    u64 acc[WIDTH];
#pragma unroll
    for (int w = 0; w < WIDTH; ++w) acc[w] = 0ull;   // (+0.0f, +0.0f)

#pragma unroll
    for (int i = 0; i < 4; ++i) {
        // LDG.128 leaves (x,y) and (z,w) in adjacent regs -> cheap packs
        u64 xp[2] = { pack2(xv[i].x, xv[i].y), pack2(xv[i].z, xv[i].w) };
#pragma unroll
        for (int p = 0; p < 2; ++p) {
            const u64 txs = mul2(xp[p], tis2);       // 2*xs = H1
            const u64 x2  = mul2(xp[p], xp[p]);
            uf2 ea; ea.u  = mul2(x2, k2);            // -log2e * xs^2
            // min(xs^2,50) never binds here (delta ~e-50 << 1e-3 tolerance)
            const u64 g   = pack2(ex2f(ea.f.x), ex2f(ea.f.y));

            acc[0] = add2(acc[0], g);                // g * H0
            acc[1] = fma2(g, txs, acc[1]);           // g * H1

            // n=2: H2 = 2xs*H1 - 2 ; clip can't bind where g > 8e-12
            u64 hm2 = txs;
            u64 h   = fma2(txs, txs, m2);            // txs^2 - 2
            acc[2]  = fma2(g, h, acc[2]);
            u64 hm1 = h;
#pragma unroll
            for (int n = 3; n <= DEGREE; ++n) {
                const float cn = -2.0f * (float)(n - 1);  // immediate
                uf2 hp; hp.u = hm2;
                const u64 t = pack2(hp.f.x * cn, hp.f.y * cn); // FMUL-imm x2
                h = fma2(txs, hm1, t);               // 2xs*hm1 - 2(n-1)*hm2
                uf2 hc; hc.u = h;                    // clip BEFORE recursion
                hc.f.x = clipf(hc.f.x);
                hc.f.y = clipf(hc.f.y);
                h = hc.u;
                acc[n] = fma2(g, h, acc[n]);
                hm2 = hm1;
                hm1 = h;
            }
        }
    }
    // collapse packed halves -> scalar accumulators
#pragma unroll
    for (int w = 0; w < WIDTH; ++w) {
        uf2 t; t.u = acc[w];
        aout[w] = t.f.x + t.f.y;
    }
}

__device__ __forceinline__ void reduce_store(float* __restrict__ a,
                                             float (*s_part)[WIDTH],
                                             int warp, int lane)
{
#pragma unroll
    for (int w = 0; w < WIDTH; ++w) {
#pragma unroll
        for (int off = 16; off > 0; off >>= 1)
            a[w] += __shfl_xor_sync(0xffffffffu, a[w], off);
    }
    if (lane == 0) {
#pragma unroll
        for (int w = 0; w < WIDTH; ++w)
            s_part[warp][w] = a[w];
    }
}

__device__ __forceinline__ void phase2(const float (*s_part)[WIDTH],
                                       const float* __restrict__ cf,
                                       float* __restrict__ out,
                                       int group, int tid)
{
#pragma unroll
    for (int r = 0; r < ROWS_PER_BLOCK; ++r) {
        float bs[WIDTH];
#pragma unroll
        for (int w = 0; w < WIDTH; ++w)
            bs[w] = s_part[2 * r][w] + s_part[2 * r + 1][w];

        float4 o;
        float* op = reinterpret_cast<float*>(&o);
#pragma unroll
        for (int i = 0; i < 4; ++i) {
            float v = 0.0f;
#pragma unroll
            for (int w = 0; w < WIDTH; ++w)
                v += bs[w] * cf[i * WIDTH + w];
            op[i] = v;
        }
        const int orow = group * ROWS_PER_BLOCK + r;
        reinterpret_cast<float4*>(out + (size_t)orow * OUTF)[tid] = o;
    }
}

// Persistent 2-group pipelined kernel (R9 shell) + packed-f32x2 eval.
__global__ __launch_bounds__(THREADS, 4)   // force regs <= 64 -> 4 blocks/SM
void hermite_fused_kernel(const float* __restrict__ x,
                          const float* __restrict__ coeffs,
                          const float* __restrict__ sigma,
                          float* __restrict__ out)
{
    __shared__ float s_partA[NWARPS][WIDTH];
    __shared__ float s_partB[NWARPS][WIDTH];

    const int tid  = threadIdx.x;
    const int lane = tid & 31;
    const int warp = tid >> 5;

    const float s     = fminf(fmaxf(sigma[0], 0.1f), 5.0f);
    const float inv_s = 1.0f / s;
    const float kexp  = -1.4426950408889634f * inv_s * inv_s;

    const u64 tis2 = pack2(2.0f * inv_s, 2.0f * inv_s);
    const u64 k2   = pack2(kexp, kexp);
    const u64 m2   = pack2(-2.0f, -2.0f);

    const int g0 = blockIdx.x;
    const int g1 = blockIdx.x + GRID;
    const bool has2 = (g1 < NGROUPS);

    const int half = warp & 1;
    const int roff = (warp >> 1);   // row within group

    // ---- group 0: load + eval ----
    const int row0 = g0 * ROWS_PER_BLOCK + roff;
    const float4* xr =
        reinterpret_cast<const float4*>(x + (size_t)row0 * FEAT)
        + half * (FEAT / 8);
    float4 xv[4];
#pragma unroll
    for (int i = 0; i < 4; ++i) xv[i] = xr[lane + 32 * i];

    float a[WIDTH];
    eval16p(xv, tis2, k2, m2, a);

    // ---- prefetch group 1's x and the coeffs (latency hidden below) ----
    float4 xv2[4];
    if (has2) {
        const int row1 = g1 * ROWS_PER_BLOCK + roff;
        const float4* xr2 =
            reinterpret_cast<const float4*>(x + (size_t)row1 * FEAT)
            + half * (FEAT / 8);
#pragma unroll
        for (int i = 0; i < 4; ++i) xv2[i] = xr2[lane + 32 * i];
    }
    float4 c[7];
    {
        const float4* c4 = reinterpret_cast<const float4*>(
            coeffs + (size_t)(tid * 4) * WIDTH);
#pragma unroll
        for (int i = 0; i < 7; ++i) c[i] = c4[i];
    }
    const float* cf = reinterpret_cast<const float*>(c);

    reduce_store(a, s_partA, warp, lane);
    __syncthreads();                       // barrier 1
    phase2(s_partA, cf, out, g0, tid);

    // ---- group 1: eval + reduce (buffer B) + phase 2 ----
    if (has2) {
        float a2[WIDTH];
        eval16p(xv2, tis2, k2, m2, a2);
        reduce_store(a2, s_partB, warp, lane);
        __syncthreads();                   // barrier 2
        phase2(s_partB, cf, out, g1, tid);
    }
}

extern "C" void kernel_launch(void* const* d_in, const int* in_sizes, int n_in,
                              void* d_out, int out_size)
{
    const float* x      = (const float*)d_in[0];   // (4096, 1024)
    const float* coeffs = (const float*)d_in[1];   // (1024, 7)
    const float* sigma  = (const float*)d_in[2];   // (1,)
    float* out          = (float*)d_out;           // (4096, 1024)

    hermite_fused_kernel<<<GRID, THREADS>>>(x, coeffs, sigma, out);
}